// round 3
// baseline (speedup 1.0000x reference)
#include <cuda_runtime.h>

#define C_DIM   16
#define DIM_IN  16
#define XPAD    20          // floats per mu1 row in shared (80B stride: avoids 2-way conflicts, keeps 16B alignment)
#define MAX_NNZ 1024
#define MAX_ROWS 256
#define MAX_PATHS 64

__device__ int   g_row_start[MAX_ROWS + 1];
__device__ int   g_row_path[MAX_ROWS];
__device__ float g_wT[MAX_PATHS * C_DIM];

// One small prep kernel per launch (deterministic, graph-capturable):
//  - transpose weights to [path][c] so the epilogue can do one float4 load
//  - build CSR row starts over the (globally sorted) mu_3 array
//  - record the single path owning each output row
__global__ void tp_prep_kernel(const float* __restrict__ weights,
                               const int* __restrict__ mu3,
                               const int* __restrict__ widx,
                               int nnz, int dim3v, int n_paths) {
    int t = threadIdx.x;
    for (int i = t; i < n_paths * C_DIM; i += blockDim.x) {
        int p = i >> 4, c = i & 15;
        g_wT[p * C_DIM + c] = weights[c * n_paths + p];
    }
    for (int m = t; m <= dim3v; m += blockDim.x) {
        int lo = 0, hi = nnz;
        while (lo < hi) {
            int mid = (lo + hi) >> 1;
            if (mu3[mid] < m) lo = mid + 1; else hi = mid;
        }
        g_row_start[m] = lo;
        if (m < dim3v && lo < nnz) g_row_path[m] = widx[lo];
    }
}

// One block per edge. 256 threads: q = tid&3 -> 4-channel group, r = tid>>2 -> row group.
// Phase 1: stage x[e] into shared (padded), build packed per-edge table
//          ent[k] = { cg[k]*y[e,mu2[k]],  byte-offset of x row mu1[k] }.
// Phase 2: per output row m3, accumulate float4 over its CSR segment, scale by
//          the path weight, store one float4 (warp stores 512B contiguous).
__global__ void __launch_bounds__(256)
tp_main_kernel(const float* __restrict__ x,
               const float* __restrict__ y,
               const float* __restrict__ cg,
               const int* __restrict__ mu1,
               const int* __restrict__ mu2,
               float* __restrict__ out,
               int nnz, int dim3v) {
    __shared__ __align__(16) float  x_sh[DIM_IN * XPAD];
    __shared__ __align__(8)  float2 ent_sh[MAX_NNZ];

    const int e = blockIdx.x;
    const int t = threadIdx.x;

    // stage x[e] : x[e][row][c] -> x_sh[row*XPAD + c]
    {
        float v = x[e * (DIM_IN * C_DIM) + t];
        x_sh[(t >> 4) * XPAD + (t & 15)] = v;
    }
    // build per-edge packed table
    const float* ye = y + e * DIM_IN;
    for (int k = t; k < nnz; k += 256) {
        float cgy = cg[k] * __ldg(&ye[mu2[k]]);
        ent_sh[k] = make_float2(cgy, __int_as_float(mu1[k] * (XPAD * 4)));
    }
    __syncthreads();

    const int q = t & 3;          // channel quad
    const int r = t >> 2;         // row group 0..63
    const char* xb = (const char*)x_sh + q * 16;
    float* outE = out + (size_t)e * dim3v * C_DIM;

    for (int m3 = r; m3 < dim3v; m3 += 64) {
        const int s  = g_row_start[m3];
        const int en = g_row_start[m3 + 1];
        float4 acc = make_float4(0.f, 0.f, 0.f, 0.f);
        #pragma unroll 4
        for (int k = s; k < en; ++k) {
            float2 ent = ent_sh[k];
            const float4 xv = *(const float4*)(xb + __float_as_int(ent.y));
            acc.x = fmaf(xv.x, ent.x, acc.x);
            acc.y = fmaf(xv.y, ent.x, acc.y);
            acc.z = fmaf(xv.z, ent.x, acc.z);
            acc.w = fmaf(xv.w, ent.x, acc.w);
        }
        const float4 wv = *(const float4*)(g_wT + g_row_path[m3] * C_DIM + q * 4);
        acc.x *= wv.x; acc.y *= wv.y; acc.z *= wv.z; acc.w *= wv.w;
        *(float4*)(outE + m3 * C_DIM + q * 4) = acc;
    }
}

extern "C" void kernel_launch(void* const* d_in, const int* in_sizes, int n_in,
                              void* d_out, int out_size) {
    const float* x      = (const float*)d_in[0];
    const float* y      = (const float*)d_in[1];
    const float* cg     = (const float*)d_in[2];
    const float* w      = (const float*)d_in[3];
    const int*   mu1    = (const int*)d_in[4];
    const int*   mu2    = (const int*)d_in[5];
    const int*   mu3    = (const int*)d_in[6];
    const int*   widx   = (const int*)d_in[7];

    const int nnz     = in_sizes[4];
    const int E       = in_sizes[1] / DIM_IN;
    const int dim3v   = out_size / (E * C_DIM);
    const int n_paths = in_sizes[3] / C_DIM;

    tp_prep_kernel<<<1, 256>>>(w, mu3, widx, nnz, dim3v, n_paths);
    tp_main_kernel<<<E, 256>>>(x, y, cg, mu1, mu2, (float*)d_out, nnz, dim3v);
}